// round 11
// baseline (speedup 1.0000x reference)
#include <cuda_runtime.h>
#include <cuda_fp16.h>
#include <cstdint>

#define B_    64
#define S_    512
#define DIN   512
#define NCAP  32
#define DCAP  64
#define EPSQ  1e-7f

// ---------------- scratch (device globals; no allocations) ----------------
__device__ __half g_Uh[B_ * S_ * DIN];         // fp16 copy of U (converted once) ~34MB
__device__ float  g_Wt[NCAP * DCAP * DIN];     // W transposed: [n][d][i]
__device__ float  g_tp[4 * B_ * DIN];          // partial column sums of U
__device__ float  g_w[B_ * DIN * NCAP];        // w[b][i][n]
__device__ __half g_ch[B_ * S_ * NCAP];        // c[b][s][n] fp16 (post-softmax)
__device__ float  g_v[B_ * NCAP * DIN];        // v[b][n][i]

// ---------------- fp16 m16n8k16 MMA ----------------
__device__ __forceinline__ void mma_f16(float& c0, float& c1, float& c2, float& c3,
                                        uint32_t a0, uint32_t a1, uint32_t a2, uint32_t a3,
                                        uint32_t b0, uint32_t b1) {
    asm("mma.sync.aligned.m16n8k16.row.col.f32.f16.f16.f32 "
        "{%0,%1,%2,%3}, {%4,%5,%6,%7}, {%8,%9}, {%0,%1,%2,%3};"
        : "+f"(c0), "+f"(c1), "+f"(c2), "+f"(c3)
        : "r"(a0), "r"(a1), "r"(a2), "r"(a3), "r"(b0), "r"(b1));
}

// ---------------- prep: blocks 0..255 transpose W; 256..511 colsum U + fp16 convert ----
__global__ __launch_bounds__(256) void prep_k(const float* __restrict__ U,
                                              const float* __restrict__ W) {
    int t = threadIdx.x;
    if (blockIdx.x < 256) {
        int n  = blockIdx.x >> 3;
        int i0 = (blockIdx.x & 7) * 64;
        __shared__ float sm[64 * 65];
        #pragma unroll
        for (int r = 0; r < 16; ++r) {
            int idx = r * 256 + t;
            int d = idx & 63, ii = idx >> 6;
            sm[d * 65 + ii] = W[(size_t)(i0 + ii) * 2048 + n * 64 + d];
        }
        __syncthreads();
        #pragma unroll
        for (int r = 0; r < 16; ++r) {
            int idx = r * 256 + t;
            int ii = idx & 63, d = idx >> 6;
            g_Wt[((size_t)n * 64 + d) * 512 + i0 + ii] = sm[d * 65 + ii];
        }
    } else {
        int idx = blockIdx.x - 256;
        int b = idx & 63, sc = idx >> 6;
        size_t base = ((size_t)b * S_ + sc * 128) * DIN;
        const float2* p = (const float2*)(U + base) + t;
        __half2* qh = (__half2*)(g_Uh + base) + t;
        float2 a = make_float2(0.f, 0.f);
        #pragma unroll 4
        for (int s = 0; s < 128; ++s) {
            float2 f = p[(size_t)s * 256];
            a.x += f.x; a.y += f.y;
            qh[(size_t)s * 256] = __floats2half2_rn(f.x, f.y);
        }
        *(float2*)(g_tp + ((size_t)sc * B_ + b) * DIN + t * 2) = a;
    }
}

// ---------------- fused out + w (fp32, unchanged) ----------------
__global__ __launch_bounds__(512) void outw_k(float* __restrict__ out, int bcast, int dow) {
    int n  = blockIdx.x;
    int b0 = blockIdx.y * 8;
    __shared__ __align__(16) float sv[8][DIN];
    __shared__ float so[8][DCAP];
    int t = threadIdx.x, w = t >> 5, lane = t & 31;
    const float* Wn = g_Wt + (size_t)n * DCAP * DIN;

    #pragma unroll
    for (int r = 0; r < 8; ++r) {
        int idx = r * 512 + t;
        int bb = idx >> 9, pos = idx & 511;
        int b = b0 + bb;
        float val;
        if (bcast)
            val = g_tp[(size_t)b * DIN + pos]
                + g_tp[((size_t)B_ + b) * DIN + pos]
                + g_tp[((size_t)2 * B_ + b) * DIN + pos]
                + g_tp[((size_t)3 * B_ + b) * DIN + pos];
        else
            val = g_v[((size_t)b * NCAP + n) * DIN + pos];
        sv[bb][pos] = val;
    }
    __syncthreads();

    #pragma unroll
    for (int r = 0; r < 4; ++r) {
        int d = r * 16 + w;
        const float4* wp = (const float4*)(Wn + (size_t)d * DIN);
        float acc[8] = {};
        #pragma unroll
        for (int q = 0; q < 4; ++q) {
            float4 wv = wp[lane + q * 32];
            #pragma unroll
            for (int bb = 0; bb < 8; ++bb) {
                float4 vv = ((const float4*)sv[bb])[lane + q * 32];
                acc[bb] += wv.x * vv.x + wv.y * vv.y + wv.z * vv.z + wv.w * vv.w;
            }
        }
        #pragma unroll
        for (int bb = 0; bb < 8; ++bb) {
            #pragma unroll
            for (int off = 16; off; off >>= 1)
                acc[bb] += __shfl_xor_sync(0xffffffffu, acc[bb], off);
        }
        if (lane == 0) {
            #pragma unroll
            for (int bb = 0; bb < 8; ++bb) so[bb][d] = acc[bb];
        }
    }
    __syncthreads();

    if (w < 8) {
        int b = b0 + w;
        float o1 = so[w][lane], o2 = so[w][lane + 32];
        if (bcast) { o1 *= (1.f / 32.f); o2 *= (1.f / 32.f); }
        float sq = o1 * o1 + o2 * o2;
        #pragma unroll
        for (int off = 16; off; off >>= 1) sq += __shfl_xor_sync(0xffffffffu, sq, off);
        float rn = rsqrtf(sq + EPSQ);
        o1 *= rn; o2 *= rn;
        out[((size_t)b * NCAP + n) * DCAP + lane]      = o1;
        out[((size_t)b * NCAP + n) * DCAP + lane + 32] = o2;
        so[w][lane]      = o1;
        so[w][lane + 32] = o2;
    }
    __syncthreads();

    if (dow) {
        int i = t;
        float acc[8] = {};
        #pragma unroll 8
        for (int d = 0; d < DCAP; ++d) {
            float wt = Wn[(size_t)d * DIN + i];
            #pragma unroll
            for (int bb = 0; bb < 8; ++bb) acc[bb] += so[bb][d] * wt;
        }
        #pragma unroll
        for (int bb = 0; bb < 8; ++bb)
            g_w[((size_t)(b0 + bb) * DIN + i) * NCAP + n] = acc[bb];
    }
}

// ---------------- fp16 MMA: logits[s,n] = U[s,:]·w[:,n], softmax fused ----------------
// grid (8 s-tiles, 64 b) = 512 blocks, 4 warps. Tile 64s x 32n; warp = 16s x 32n.
__global__ __launch_bounds__(128, 4) void blogmma_k() {
    int s0 = blockIdx.x * 64;
    int b  = blockIdx.y;
    __shared__ __align__(16) __half su[64 * 40];   // [s][k], stride 40
    __shared__ __align__(16) __half sw[32 * 40];   // [n][k]
    int t = threadIdx.x, w = t >> 5, lane = t & 31;
    int g = lane >> 2, tg = lane & 3;
    int wrow = w * 16;
    int lr = t >> 2, lq = t & 3;    // loader coords
    const __half* Ub = g_Uh + ((size_t)b * S_ + s0) * DIN;
    const float*  wb = g_w  + (size_t)b * DIN * NCAP;
    float c[4][4] = {};
    uint4 pu[2];
    float4 pw[2];
    pu[0] = *(const uint4*)(Ub + (size_t)lr * DIN + lq * 8);
    pu[1] = *(const uint4*)(Ub + (size_t)(lr + 32) * DIN + lq * 8);
    pw[0] = *(const float4*)(wb + (size_t)lr * NCAP + lq * 8);
    pw[1] = *(const float4*)(wb + (size_t)lr * NCAP + lq * 8 + 4);

    #pragma unroll 1
    for (int ch = 0; ch < 16; ++ch) {
        __syncthreads();
        *(uint4*)&su[(size_t)lr * 40 + lq * 8]        = pu[0];
        *(uint4*)&su[(size_t)(lr + 32) * 40 + lq * 8] = pu[1];
        {   // w tile: rows k, transposed into [n][k], fp16
            float wf[8] = {pw[0].x, pw[0].y, pw[0].z, pw[0].w,
                           pw[1].x, pw[1].y, pw[1].z, pw[1].w};
            #pragma unroll
            for (int j = 0; j < 8; ++j)
                sw[(lq * 8 + j) * 40 + lr] = __float2half_rn(wf[j]);
        }
        __syncthreads();
        if (ch < 15) {
            int k0 = (ch + 1) * 32;
            pu[0] = *(const uint4*)(Ub + (size_t)lr * DIN + k0 + lq * 8);
            pu[1] = *(const uint4*)(Ub + (size_t)(lr + 32) * DIN + k0 + lq * 8);
            pw[0] = *(const float4*)(wb + (size_t)(k0 + lr) * NCAP + lq * 8);
            pw[1] = *(const float4*)(wb + (size_t)(k0 + lr) * NCAP + lq * 8 + 4);
        }
        #pragma unroll
        for (int ks = 0; ks < 32; ks += 16) {
            uint32_t a0 = *(const uint32_t*)&su[(wrow + g)     * 40 + ks + 2 * tg];
            uint32_t a1 = *(const uint32_t*)&su[(wrow + g + 8) * 40 + ks + 2 * tg];
            uint32_t a2 = *(const uint32_t*)&su[(wrow + g)     * 40 + ks + 2 * tg + 8];
            uint32_t a3 = *(const uint32_t*)&su[(wrow + g + 8) * 40 + ks + 2 * tg + 8];
            #pragma unroll
            for (int nt = 0; nt < 4; ++nt) {
                uint32_t b0 = *(const uint32_t*)&sw[(nt * 8 + g) * 40 + ks + 2 * tg];
                uint32_t b1 = *(const uint32_t*)&sw[(nt * 8 + g) * 40 + ks + 2 * tg + 8];
                mma_f16(c[nt][0], c[nt][1], c[nt][2], c[nt][3],
                        a0, a1, a2, a3, b0, b1);
            }
        }
    }
    // softmax over n per s-row (row's 32 n on 4 lanes sharing g: xor 1,2); fp16 store
    __half* cbase = g_ch + ((size_t)b * S_ + s0) * NCAP;
    #pragma unroll
    for (int half = 0; half < 2; ++half) {
        int row = wrow + g + half * 8;
        float v0 = c[0][half * 2], v1 = c[0][half * 2 + 1];
        float v2 = c[1][half * 2], v3 = c[1][half * 2 + 1];
        float v4 = c[2][half * 2], v5 = c[2][half * 2 + 1];
        float v6 = c[3][half * 2], v7 = c[3][half * 2 + 1];
        float m = fmaxf(fmaxf(fmaxf(v0, v1), fmaxf(v2, v3)),
                        fmaxf(fmaxf(v4, v5), fmaxf(v6, v7)));
        m = fmaxf(m, __shfl_xor_sync(0xffffffffu, m, 1));
        m = fmaxf(m, __shfl_xor_sync(0xffffffffu, m, 2));
        float e0 = __expf(v0 - m), e1 = __expf(v1 - m), e2 = __expf(v2 - m), e3 = __expf(v3 - m);
        float e4 = __expf(v4 - m), e5 = __expf(v5 - m), e6 = __expf(v6 - m), e7 = __expf(v7 - m);
        float sm = e0 + e1 + e2 + e3 + e4 + e5 + e6 + e7;
        sm += __shfl_xor_sync(0xffffffffu, sm, 1);
        sm += __shfl_xor_sync(0xffffffffu, sm, 2);
        float inv = 1.f / sm;
        __half2* cr = (__half2*)(cbase + (size_t)row * NCAP + 2 * tg);
        cr[0]  = __floats2half2_rn(e0 * inv, e1 * inv);
        cr[4]  = __floats2half2_rn(e2 * inv, e3 * inv);
        cr[8]  = __floats2half2_rn(e4 * inv, e5 * inv);
        cr[12] = __floats2half2_rn(e6 * inv, e7 * inv);
    }
}

// ---------------- fp16 MMA: v[n,i] = sum_s c[s,n] U[s,i] (v^T then transpose) ----------
// grid (8 i-tiles, 64 b) = 512 blocks, 4 warps. Tile 64i x 32n; warp = 16i x 32n.
__global__ __launch_bounds__(128, 4) void vmma_k() {
    int i0 = blockIdx.x * 64;
    int b  = blockIdx.y;
    __shared__ __align__(16) unsigned char smraw[8448 * 4 > 7680 ? 8448 * 4 : 7680];
    __half* sut = (__half*)smraw;                 // [i][s] 64x40 halfs (5120B)
    __half* scm = (__half*)(smraw + 5120);        // [n][s] 32x40 halfs (2560B)
    float*  vsm = (float*)smraw;                  // epilogue reuse: 64x33 floats (8448B)
    int t = threadIdx.x, w = t >> 5, lane = t & 31;
    int g = lane >> 2, tg = lane & 3;
    int wi = w * 16;
    int lr = t >> 2, lq = t & 3;
    const __half* Ub = g_Uh + (size_t)b * S_ * DIN;
    const __half* cb = g_ch + (size_t)b * S_ * NCAP;
    float c[4][4] = {};
    uint4 pu[2], pc;
    #pragma unroll
    for (int r = 0; r < 2; ++r)
        pu[r] = *(const uint4*)(Ub + (size_t)lr * DIN + i0 + (lq + 4 * r) * 8);
    pc = *(const uint4*)(cb + (size_t)lr * NCAP + lq * 8);

    #pragma unroll 1
    for (int ch = 0; ch < 16; ++ch) {
        __syncthreads();
        #pragma unroll
        for (int r = 0; r < 2; ++r) {   // transpose-stage U: [s][i] -> sut[i][s]
            const __half* h = (const __half*)&pu[r];
            int ib = (lq + 4 * r) * 8;
            #pragma unroll
            for (int j = 0; j < 8; ++j)
                sut[(ib + j) * 40 + lr] = h[j];
        }
        {   // transpose-stage c: [s][n] -> scm[n][s]
            const __half* h = (const __half*)&pc;
            #pragma unroll
            for (int j = 0; j < 8; ++j)
                scm[(lq * 8 + j) * 40 + lr] = h[j];
        }
        __syncthreads();
        if (ch < 15) {
            int s1 = (ch + 1) * 32;
            #pragma unroll
            for (int r = 0; r < 2; ++r)
                pu[r] = *(const uint4*)(Ub + (size_t)(s1 + lr) * DIN + i0 + (lq + 4 * r) * 8);
            pc = *(const uint4*)(cb + (size_t)(s1 + lr) * NCAP + lq * 8);
        }
        #pragma unroll
        for (int ks = 0; ks < 32; ks += 16) {
            uint32_t a0 = *(const uint32_t*)&sut[(wi + g)     * 40 + ks + 2 * tg];
            uint32_t a1 = *(const uint32_t*)&sut[(wi + g + 8) * 40 + ks + 2 * tg];
            uint32_t a2 = *(const uint32_t*)&sut[(wi + g)     * 40 + ks + 2 * tg + 8];
            uint32_t a3 = *(const uint32_t*)&sut[(wi + g + 8) * 40 + ks + 2 * tg + 8];
            #pragma unroll
            for (int nt = 0; nt < 4; ++nt) {
                uint32_t b0 = *(const uint32_t*)&scm[(nt * 8 + g) * 40 + ks + 2 * tg];
                uint32_t b1 = *(const uint32_t*)&scm[(nt * 8 + g) * 40 + ks + 2 * tg + 8];
                mma_f16(c[nt][0], c[nt][1], c[nt][2], c[nt][3],
                        a0, a1, a2, a3, b0, b1);
            }
        }
    }
    // transpose v^T[i][n] -> v[n][i] via smem, coalesced store
    __syncthreads();
    #pragma unroll
    for (int nt = 0; nt < 4; ++nt) {
        int nc = nt * 8 + 2 * tg;
        vsm[(wi + g)     * 33 + nc]     = c[nt][0];
        vsm[(wi + g)     * 33 + nc + 1] = c[nt][1];
        vsm[(wi + g + 8) * 33 + nc]     = c[nt][2];
        vsm[(wi + g + 8) * 33 + nc + 1] = c[nt][3];
    }
    __syncthreads();
    {
        int n = t >> 2, igrp = t & 3;
        float* vb = g_v + ((size_t)b * NCAP + n) * DIN + i0;
        #pragma unroll
        for (int q = 0; q < 4; ++q) {
            int i4 = igrp * 4 + q * 16;
            float4 o = make_float4(vsm[(i4 + 0) * 33 + n], vsm[(i4 + 1) * 33 + n],
                                   vsm[(i4 + 2) * 33 + n], vsm[(i4 + 3) * 33 + n]);
            *(float4*)(vb + i4) = o;
        }
    }
}

// ---------------- launch ----------------
extern "C" void kernel_launch(void* const* d_in, const int* in_sizes, int n_in,
                              void* d_out, int out_size) {
    const float* U = (const float*)d_in[0];   // (64, 512, 512)
    const float* W = (const float*)d_in[1];   // (512, 2048)
    float* out = (float*)d_out;               // (64, 32, 64)

    prep_k<<<512, 256>>>(U, W);
    outw_k<<<dim3(32, 8), 512>>>(out, 1, 1);             // iteration 0 + w0
    for (int it = 0; it < 2; ++it) {
        blogmma_k<<<dim3(8, 64), 128>>>();
        vmma_k<<<dim3(8, 64), 128>>>();
        outw_k<<<dim3(32, 8), 512>>>(out, 0, it == 0);   // out + (w for iter 1 only)
    }
}

// round 13
// speedup vs baseline: 1.2222x; 1.2222x over previous
#include <cuda_runtime.h>
#include <cuda_fp16.h>
#include <cstdint>

#define B_    64
#define S_    512
#define DIN   512
#define NCAP  32
#define DCAP  64
#define EPSQ  1e-7f

// ---------------- scratch (device globals; no allocations) ----------------
__device__ __half g_Uh[B_ * S_ * DIN];         // fp16 copy of U (converted once) ~34MB
__device__ float  g_Wt[NCAP * DCAP * DIN];     // W transposed: [n][d][i]
__device__ float  g_tp[4 * B_ * DIN];          // partial column sums of U
__device__ float  g_w[B_ * DIN * NCAP];        // w[b][i][n]
__device__ __half g_ch[B_ * S_ * NCAP];        // c[b][s][n] fp16 (post-softmax)
__device__ float  g_v[B_ * NCAP * DIN];        // v[b][n][i]

// ---------------- mma / ldmatrix helpers ----------------
__device__ __forceinline__ uint32_t h2u(__half2 h) {
    union { __half2 h; uint32_t u; } cvt;
    cvt.h = h;
    return cvt.u;
}
__device__ __forceinline__ void mma_f16(float& c0, float& c1, float& c2, float& c3,
                                        uint32_t a0, uint32_t a1, uint32_t a2, uint32_t a3,
                                        uint32_t b0, uint32_t b1) {
    asm("mma.sync.aligned.m16n8k16.row.col.f32.f16.f16.f32 "
        "{%0,%1,%2,%3}, {%4,%5,%6,%7}, {%8,%9}, {%0,%1,%2,%3};"
        : "+f"(c0), "+f"(c1), "+f"(c2), "+f"(c3)
        : "r"(a0), "r"(a1), "r"(a2), "r"(a3), "r"(b0), "r"(b1));
}
__device__ __forceinline__ uint32_t s2u(const void* p) {
    return (uint32_t)__cvta_generic_to_shared(p);
}
__device__ __forceinline__ void ldsm4(uint32_t& r0, uint32_t& r1, uint32_t& r2, uint32_t& r3,
                                      uint32_t addr) {
    asm volatile("ldmatrix.sync.aligned.m8n8.x4.shared.b16 {%0,%1,%2,%3}, [%4];"
                 : "=r"(r0), "=r"(r1), "=r"(r2), "=r"(r3) : "r"(addr));
}
__device__ __forceinline__ void ldsm4t(uint32_t& r0, uint32_t& r1, uint32_t& r2, uint32_t& r3,
                                       uint32_t addr) {
    asm volatile("ldmatrix.sync.aligned.m8n8.x4.trans.shared.b16 {%0,%1,%2,%3}, [%4];"
                 : "=r"(r0), "=r"(r1), "=r"(r2), "=r"(r3) : "r"(addr));
}

// ---------------- prep: blocks 0..255 transpose W; 256..511 colsum U + fp16 convert ----
__global__ __launch_bounds__(256) void prep_k(const float* __restrict__ U,
                                              const float* __restrict__ W) {
    int t = threadIdx.x;
    if (blockIdx.x < 256) {
        int n  = blockIdx.x >> 3;
        int i0 = (blockIdx.x & 7) * 64;
        __shared__ float sm[64 * 65];
        #pragma unroll
        for (int r = 0; r < 16; ++r) {
            int idx = r * 256 + t;
            int d = idx & 63, ii = idx >> 6;
            sm[d * 65 + ii] = W[(size_t)(i0 + ii) * 2048 + n * 64 + d];
        }
        __syncthreads();
        #pragma unroll
        for (int r = 0; r < 16; ++r) {
            int idx = r * 256 + t;
            int ii = idx & 63, d = idx >> 6;
            g_Wt[((size_t)n * 64 + d) * 512 + i0 + ii] = sm[d * 65 + ii];
        }
    } else {
        int idx = blockIdx.x - 256;
        int b = idx & 63, sc = idx >> 6;
        size_t base = ((size_t)b * S_ + sc * 128) * DIN;
        const float2* p = (const float2*)(U + base) + t;
        __half2* qh = (__half2*)(g_Uh + base) + t;
        float2 a = make_float2(0.f, 0.f);
        #pragma unroll 4
        for (int s = 0; s < 128; ++s) {
            float2 f = p[(size_t)s * 256];
            a.x += f.x; a.y += f.y;
            qh[(size_t)s * 256] = __floats2half2_rn(f.x, f.y);
        }
        *(float2*)(g_tp + ((size_t)sc * B_ + b) * DIN + t * 2) = a;
    }
}

// ---------------- fused out + w (fp32, unchanged) ----------------
__global__ __launch_bounds__(512) void outw_k(float* __restrict__ out, int bcast, int dow) {
    int n  = blockIdx.x;
    int b0 = blockIdx.y * 8;
    __shared__ __align__(16) float sv[8][DIN];
    __shared__ float so[8][DCAP];
    int t = threadIdx.x, w = t >> 5, lane = t & 31;
    const float* Wn = g_Wt + (size_t)n * DCAP * DIN;

    #pragma unroll
    for (int r = 0; r < 8; ++r) {
        int idx = r * 512 + t;
        int bb = idx >> 9, pos = idx & 511;
        int b = b0 + bb;
        float val;
        if (bcast)
            val = g_tp[(size_t)b * DIN + pos]
                + g_tp[((size_t)B_ + b) * DIN + pos]
                + g_tp[((size_t)2 * B_ + b) * DIN + pos]
                + g_tp[((size_t)3 * B_ + b) * DIN + pos];
        else
            val = g_v[((size_t)b * NCAP + n) * DIN + pos];
        sv[bb][pos] = val;
    }
    __syncthreads();

    #pragma unroll
    for (int r = 0; r < 4; ++r) {
        int d = r * 16 + w;
        const float4* wp = (const float4*)(Wn + (size_t)d * DIN);
        float acc[8] = {};
        #pragma unroll
        for (int q = 0; q < 4; ++q) {
            float4 wv = wp[lane + q * 32];
            #pragma unroll
            for (int bb = 0; bb < 8; ++bb) {
                float4 vv = ((const float4*)sv[bb])[lane + q * 32];
                acc[bb] += wv.x * vv.x + wv.y * vv.y + wv.z * vv.z + wv.w * vv.w;
            }
        }
        #pragma unroll
        for (int bb = 0; bb < 8; ++bb) {
            #pragma unroll
            for (int off = 16; off; off >>= 1)
                acc[bb] += __shfl_xor_sync(0xffffffffu, acc[bb], off);
        }
        if (lane == 0) {
            #pragma unroll
            for (int bb = 0; bb < 8; ++bb) so[bb][d] = acc[bb];
        }
    }
    __syncthreads();

    if (w < 8) {
        int b = b0 + w;
        float o1 = so[w][lane], o2 = so[w][lane + 32];
        if (bcast) { o1 *= (1.f / 32.f); o2 *= (1.f / 32.f); }
        float sq = o1 * o1 + o2 * o2;
        #pragma unroll
        for (int off = 16; off; off >>= 1) sq += __shfl_xor_sync(0xffffffffu, sq, off);
        float rn = rsqrtf(sq + EPSQ);
        o1 *= rn; o2 *= rn;
        out[((size_t)b * NCAP + n) * DCAP + lane]      = o1;
        out[((size_t)b * NCAP + n) * DCAP + lane + 32] = o2;
        so[w][lane]      = o1;
        so[w][lane + 32] = o2;
    }
    __syncthreads();

    if (dow) {
        int i = t;
        float acc[8] = {};
        #pragma unroll 8
        for (int d = 0; d < DCAP; ++d) {
            float wt = Wn[(size_t)d * DIN + i];
            #pragma unroll
            for (int bb = 0; bb < 8; ++bb) acc[bb] += so[bb][d] * wt;
        }
        #pragma unroll
        for (int bb = 0; bb < 8; ++bb)
            g_w[((size_t)(b0 + bb) * DIN + i) * NCAP + n] = acc[bb];
    }
}

// ---------------- fp16 MMA: logits[s,n] = U[s,:]·w[:,n], softmax fused ----------------
// grid (4 s-tiles, 64 b), block 128 (4 warps). Tile 128s x 32n, K=512 in chunks of 32.
// A = su[s][k] via ldmatrix; B = sw[k][n] via ldmatrix.trans.
__global__ __launch_bounds__(128, 4) void blogmma_k() {
    int s0 = blockIdx.x * 128;
    int b  = blockIdx.y;
    __shared__ __align__(16) __half su[128 * 40];  // [s][k], stride 40
    __shared__ __align__(16) __half sw[32 * 40];   // [k][n], stride 40
    int t = threadIdx.x, w = t >> 5, lane = t & 31;
    int g = lane >> 2, tg = lane & 3;
    int wrow = w * 32;
    int lr = t >> 2, lq = t & 3;    // loader coords
    const __half* Ub = g_Uh + ((size_t)b * S_ + s0) * DIN;
    const float*  wb = g_w  + (size_t)b * DIN * NCAP;
    // ldmatrix lane address offsets (constant per lane)
    int arow = (lane & 7) + ((lane >> 3) & 1) * 8, acol = (lane >> 4) * 8;          // A (non-trans)
    int brow = (lane & 7) + ((lane >> 3) & 1) * 8, bcol = (lane >> 4) * 8;          // B (trans)
    float c[2][4][4] = {};
    uint4 pu[4];
    float4 pw[2];
    #pragma unroll
    for (int r = 0; r < 4; ++r)
        pu[r] = *(const uint4*)(Ub + (size_t)(lr + 32 * r) * DIN + lq * 8);
    pw[0] = *(const float4*)(wb + (size_t)lr * NCAP + lq * 8);
    pw[1] = *(const float4*)(wb + (size_t)lr * NCAP + lq * 8 + 4);

    #pragma unroll 1
    for (int ch = 0; ch < 16; ++ch) {
        __syncthreads();
        #pragma unroll
        for (int r = 0; r < 4; ++r)
            *(uint4*)&su[(lr + 32 * r) * 40 + lq * 8] = pu[r];
        {   // w tile [k][n]: convert 8 floats -> uint4 of half2
            uint4 hp;
            hp.x = h2u(__floats2half2_rn(pw[0].x, pw[0].y));
            hp.y = h2u(__floats2half2_rn(pw[0].z, pw[0].w));
            hp.z = h2u(__floats2half2_rn(pw[1].x, pw[1].y));
            hp.w = h2u(__floats2half2_rn(pw[1].z, pw[1].w));
            *(uint4*)&sw[lr * 40 + lq * 8] = hp;
        }
        __syncthreads();
        if (ch < 15) {
            int k0 = (ch + 1) * 32;
            #pragma unroll
            for (int r = 0; r < 4; ++r)
                pu[r] = *(const uint4*)(Ub + (size_t)(lr + 32 * r) * DIN + k0 + lq * 8);
            pw[0] = *(const float4*)(wb + (size_t)(k0 + lr) * NCAP + lq * 8);
            pw[1] = *(const float4*)(wb + (size_t)(k0 + lr) * NCAP + lq * 8 + 4);
        }
        #pragma unroll
        for (int ks = 0; ks < 32; ks += 16) {
            uint32_t a[2][4], bb2[2][4];
            #pragma unroll
            for (int mt = 0; mt < 2; ++mt)
                ldsm4(a[mt][0], a[mt][1], a[mt][2], a[mt][3],
                      s2u(&su[(wrow + mt * 16 + arow) * 40 + ks + acol]));
            #pragma unroll
            for (int np = 0; np < 2; ++np)
                ldsm4t(bb2[np][0], bb2[np][1], bb2[np][2], bb2[np][3],
                       s2u(&sw[(ks + brow) * 40 + np * 16 + bcol]));
            #pragma unroll
            for (int mt = 0; mt < 2; ++mt)
                #pragma unroll
                for (int np = 0; np < 2; ++np) {
                    mma_f16(c[mt][2 * np][0], c[mt][2 * np][1], c[mt][2 * np][2], c[mt][2 * np][3],
                            a[mt][0], a[mt][1], a[mt][2], a[mt][3], bb2[np][0], bb2[np][1]);
                    mma_f16(c[mt][2 * np + 1][0], c[mt][2 * np + 1][1],
                            c[mt][2 * np + 1][2], c[mt][2 * np + 1][3],
                            a[mt][0], a[mt][1], a[mt][2], a[mt][3], bb2[np][2], bb2[np][3]);
                }
        }
    }
    // softmax over n per s-row (row's 32 n on 4 lanes sharing g: xor 1,2); fp16 store
    __half* cbase = g_ch + ((size_t)b * S_ + s0) * NCAP;
    #pragma unroll
    for (int mt = 0; mt < 2; ++mt) {
        #pragma unroll
        for (int half = 0; half < 2; ++half) {
            int row = wrow + mt * 16 + g + half * 8;
            float v0 = c[mt][0][half * 2], v1 = c[mt][0][half * 2 + 1];
            float v2 = c[mt][1][half * 2], v3 = c[mt][1][half * 2 + 1];
            float v4 = c[mt][2][half * 2], v5 = c[mt][2][half * 2 + 1];
            float v6 = c[mt][3][half * 2], v7 = c[mt][3][half * 2 + 1];
            float m = fmaxf(fmaxf(fmaxf(v0, v1), fmaxf(v2, v3)),
                            fmaxf(fmaxf(v4, v5), fmaxf(v6, v7)));
            m = fmaxf(m, __shfl_xor_sync(0xffffffffu, m, 1));
            m = fmaxf(m, __shfl_xor_sync(0xffffffffu, m, 2));
            float e0 = __expf(v0 - m), e1 = __expf(v1 - m), e2 = __expf(v2 - m), e3 = __expf(v3 - m);
            float e4 = __expf(v4 - m), e5 = __expf(v5 - m), e6 = __expf(v6 - m), e7 = __expf(v7 - m);
            float sm = e0 + e1 + e2 + e3 + e4 + e5 + e6 + e7;
            sm += __shfl_xor_sync(0xffffffffu, sm, 1);
            sm += __shfl_xor_sync(0xffffffffu, sm, 2);
            float inv = 1.f / sm;
            __half2* cr = (__half2*)(cbase + (size_t)row * NCAP + 2 * tg);
            cr[0]  = __floats2half2_rn(e0 * inv, e1 * inv);
            cr[4]  = __floats2half2_rn(e2 * inv, e3 * inv);
            cr[8]  = __floats2half2_rn(e4 * inv, e5 * inv);
            cr[12] = __floats2half2_rn(e6 * inv, e7 * inv);
        }
    }
}

// ---------------- fp16 MMA: v[n,i] = sum_s c[s,n] U[s,i] (v^T then transpose) ----------
// grid (4 i-tiles, 64 b), block 128 (4 warps). Tile 128i x 32n, K=s=512 in chunks of 32.
// A = U^T via ldmatrix.trans of su[s][i]; B = c^T via ldmatrix.trans of sc[s][n].
__global__ __launch_bounds__(128, 4) void vmma_k() {
    int i0 = blockIdx.x * 128;
    int b  = blockIdx.y;
    __shared__ __align__(16) unsigned char smraw[16896];
    __half* su = (__half*)smraw;                  // [s][i] 32 x 136 halfs (8704B)
    __half* sc = (__half*)(smraw + 8704);         // [s][n] 32 x 40 halfs (2560B)
    float* vsm = (float*)smraw;                   // epilogue reuse: 128x33 floats (16896B)
    int t = threadIdx.x, w = t >> 5, lane = t & 31;
    int g = lane >> 2, tg = lane & 3;
    int wi = w * 32;
    int lr = t >> 2, lq = t & 3;
    // ldmatrix.trans lane offsets
    int tarow = (lane & 7) + ((lane >> 4) & 1) * 8, tacol = ((lane >> 3) & 1) * 8;  // A (trans)
    int tbrow = (lane & 7) + ((lane >> 3) & 1) * 8, tbcol = (lane >> 4) * 8;        // B (trans)
    const __half* Ub = g_Uh + (size_t)b * S_ * DIN;
    const __half* cb = g_ch + (size_t)b * S_ * NCAP;
    float c[2][4][4] = {};
    uint4 pu[4], pc;
    #pragma unroll
    for (int r = 0; r < 4; ++r)
        pu[r] = *(const uint4*)(Ub + (size_t)lr * DIN + i0 + (lq + 4 * r) * 8);
    pc = *(const uint4*)(cb + (size_t)lr * NCAP + lq * 8);

    #pragma unroll 1
    for (int ch = 0; ch < 16; ++ch) {
        __syncthreads();
        #pragma unroll
        for (int r = 0; r < 4; ++r)
            *(uint4*)&su[lr * 136 + (lq + 4 * r) * 8] = pu[r];
        *(uint4*)&sc[lr * 40 + lq * 8] = pc;
        __syncthreads();
        if (ch < 15) {
            int s1 = (ch + 1) * 32;
            #pragma unroll
            for (int r = 0; r < 4; ++r)
                pu[r] = *(const uint4*)(Ub + (size_t)(s1 + lr) * DIN + i0 + (lq + 4 * r) * 8);
            pc = *(const uint4*)(cb + (size_t)(s1 + lr) * NCAP + lq * 8);
        }
        #pragma unroll
        for (int ks = 0; ks < 32; ks += 16) {
            uint32_t a[2][4], bb2[2][4];
            #pragma unroll
            for (int mt = 0; mt < 2; ++mt)
                ldsm4t(a[mt][0], a[mt][1], a[mt][2], a[mt][3],
                       s2u(&su[(ks + tarow) * 136 + wi + mt * 16 + tacol]));
            #pragma unroll
            for (int np = 0; np < 2; ++np)
                ldsm4t(bb2[np][0], bb2[np][1], bb2[np][2], bb2[np][3],
                       s2u(&sc[(ks + tbrow) * 40 + np * 16 + tbcol]));
            #pragma unroll
            for (int mt = 0; mt < 2; ++mt)
                #pragma unroll
                for (int np = 0; np < 2; ++np) {
                    mma_f16(c[mt][2 * np][0], c[mt][2 * np][1], c[mt][2 * np][2], c[mt][2 * np][3],
                            a[mt][0], a[mt][1], a[mt][2], a[mt][3], bb2[np][0], bb2[np][1]);
                    mma_f16(c[mt][2 * np + 1][0], c[mt][2 * np + 1][1],
                            c[mt][2 * np + 1][2], c[mt][2 * np + 1][3],
                            a[mt][0], a[mt][1], a[mt][2], a[mt][3], bb2[np][2], bb2[np][3]);
                }
        }
    }
    // transpose v^T[i][n] -> v[n][i] via smem, coalesced store
    __syncthreads();
    #pragma unroll
    for (int mt = 0; mt < 2; ++mt) {
        int ib = wi + mt * 16;
        #pragma unroll
        for (int nt = 0; nt < 4; ++nt) {
            int nc = nt * 8 + 2 * tg;
            vsm[(ib + g)     * 33 + nc]     = c[mt][nt][0];
            vsm[(ib + g)     * 33 + nc + 1] = c[mt][nt][1];
            vsm[(ib + g + 8) * 33 + nc]     = c[mt][nt][2];
            vsm[(ib + g + 8) * 33 + nc + 1] = c[mt][nt][3];
        }
    }
    __syncthreads();
    {
        int n = t >> 2, igrp = t & 3;
        float* vb = g_v + ((size_t)b * NCAP + n) * DIN + i0;
        #pragma unroll
        for (int q = 0; q < 8; ++q) {
            int i4 = igrp * 4 + q * 16;
            float4 o = make_float4(vsm[(i4 + 0) * 33 + n], vsm[(i4 + 1) * 33 + n],
                                   vsm[(i4 + 2) * 33 + n], vsm[(i4 + 3) * 33 + n]);
            *(float4*)(vb + i4) = o;
        }
    }
}

// ---------------- launch ----------------
extern "C" void kernel_launch(void* const* d_in, const int* in_sizes, int n_in,
                              void* d_out, int out_size) {
    const float* U = (const float*)d_in[0];   // (64, 512, 512)
    const float* W = (const float*)d_in[1];   // (512, 2048)
    float* out = (float*)d_out;               // (64, 32, 64)

    prep_k<<<512, 256>>>(U, W);
    outw_k<<<dim3(32, 8), 512>>>(out, 1, 1);             // iteration 0 + w0
    for (int it = 0; it < 2; ++it) {
        blogmma_k<<<dim3(4, 64), 128>>>();
        vmma_k<<<dim3(4, 64), 128>>>();
        outw_k<<<dim3(32, 8), 512>>>(out, 0, it == 0);   // out + (w for iter 1 only)
    }
}

// round 14
// speedup vs baseline: 1.2375x; 1.0125x over previous
#include <cuda_runtime.h>
#include <cuda_fp16.h>
#include <cstdint>

#define B_    64
#define S_    512
#define DIN   512
#define NCAP  32
#define DCAP  64
#define EPSQ  1e-7f

// ---------------- scratch (device globals; no allocations) ----------------
__device__ __half g_Uh[B_ * S_ * DIN];         // fp16 copy of U (converted once) ~34MB
__device__ float  g_Wt[NCAP * DCAP * DIN];     // W transposed: [n][d][i]
__device__ float  g_tp[4 * B_ * DIN];          // partial column sums of U
__device__ float  g_w[B_ * DIN * NCAP];        // w[b][i][n]
__device__ __half g_ch[B_ * S_ * NCAP];        // c[b][s][n] fp16 (post-softmax)
__device__ float  g_v[B_ * NCAP * DIN];        // v[b][n][i]

// ---------------- mma / ldmatrix helpers ----------------
__device__ __forceinline__ uint32_t h2u(__half2 h) {
    union { __half2 h; uint32_t u; } cvt;
    cvt.h = h;
    return cvt.u;
}
__device__ __forceinline__ void mma_f16(float& c0, float& c1, float& c2, float& c3,
                                        uint32_t a0, uint32_t a1, uint32_t a2, uint32_t a3,
                                        uint32_t b0, uint32_t b1) {
    asm("mma.sync.aligned.m16n8k16.row.col.f32.f16.f16.f32 "
        "{%0,%1,%2,%3}, {%4,%5,%6,%7}, {%8,%9}, {%0,%1,%2,%3};"
        : "+f"(c0), "+f"(c1), "+f"(c2), "+f"(c3)
        : "r"(a0), "r"(a1), "r"(a2), "r"(a3), "r"(b0), "r"(b1));
}
__device__ __forceinline__ uint32_t s2u(const void* p) {
    return (uint32_t)__cvta_generic_to_shared(p);
}
__device__ __forceinline__ void ldsm4(uint32_t& r0, uint32_t& r1, uint32_t& r2, uint32_t& r3,
                                      uint32_t addr) {
    asm volatile("ldmatrix.sync.aligned.m8n8.x4.shared.b16 {%0,%1,%2,%3}, [%4];"
                 : "=r"(r0), "=r"(r1), "=r"(r2), "=r"(r3) : "r"(addr));
}
__device__ __forceinline__ void ldsm4t(uint32_t& r0, uint32_t& r1, uint32_t& r2, uint32_t& r3,
                                       uint32_t addr) {
    asm volatile("ldmatrix.sync.aligned.m8n8.x4.trans.shared.b16 {%0,%1,%2,%3}, [%4];"
                 : "=r"(r0), "=r"(r1), "=r"(r2), "=r"(r3) : "r"(addr));
}

// ---------------- prep: blocks 0..255 transpose W; 256..511 colsum U + fp16 convert ----
__global__ __launch_bounds__(256) void prep_k(const float* __restrict__ U,
                                              const float* __restrict__ W) {
    int t = threadIdx.x;
    if (blockIdx.x < 256) {
        int n  = blockIdx.x >> 3;
        int i0 = (blockIdx.x & 7) * 64;
        __shared__ float sm[64 * 65];
        #pragma unroll
        for (int r = 0; r < 16; ++r) {
            int idx = r * 256 + t;
            int d = idx & 63, ii = idx >> 6;
            sm[d * 65 + ii] = W[(size_t)(i0 + ii) * 2048 + n * 64 + d];
        }
        __syncthreads();
        #pragma unroll
        for (int r = 0; r < 16; ++r) {
            int idx = r * 256 + t;
            int ii = idx & 63, d = idx >> 6;
            g_Wt[((size_t)n * 64 + d) * 512 + i0 + ii] = sm[d * 65 + ii];
        }
    } else {
        int idx = blockIdx.x - 256;
        int b = idx & 63, sc = idx >> 6;
        size_t base = ((size_t)b * S_ + sc * 128) * DIN;
        const float2* p = (const float2*)(U + base) + t;
        __half2* qh = (__half2*)(g_Uh + base) + t;
        float2 a = make_float2(0.f, 0.f);
        #pragma unroll 4
        for (int s = 0; s < 128; ++s) {
            float2 f = p[(size_t)s * 256];
            a.x += f.x; a.y += f.y;
            qh[(size_t)s * 256] = __floats2half2_rn(f.x, f.y);
        }
        *(float2*)(g_tp + ((size_t)sc * B_ + b) * DIN + t * 2) = a;
    }
}

// ---------------- fused out + w (fp32, unchanged) ----------------
__global__ __launch_bounds__(512) void outw_k(float* __restrict__ out, int bcast, int dow) {
    int n  = blockIdx.x;
    int b0 = blockIdx.y * 8;
    __shared__ __align__(16) float sv[8][DIN];
    __shared__ float so[8][DCAP];
    int t = threadIdx.x, w = t >> 5, lane = t & 31;
    const float* Wn = g_Wt + (size_t)n * DCAP * DIN;

    #pragma unroll
    for (int r = 0; r < 8; ++r) {
        int idx = r * 512 + t;
        int bb = idx >> 9, pos = idx & 511;
        int b = b0 + bb;
        float val;
        if (bcast)
            val = g_tp[(size_t)b * DIN + pos]
                + g_tp[((size_t)B_ + b) * DIN + pos]
                + g_tp[((size_t)2 * B_ + b) * DIN + pos]
                + g_tp[((size_t)3 * B_ + b) * DIN + pos];
        else
            val = g_v[((size_t)b * NCAP + n) * DIN + pos];
        sv[bb][pos] = val;
    }
    __syncthreads();

    #pragma unroll
    for (int r = 0; r < 4; ++r) {
        int d = r * 16 + w;
        const float4* wp = (const float4*)(Wn + (size_t)d * DIN);
        float acc[8] = {};
        #pragma unroll
        for (int q = 0; q < 4; ++q) {
            float4 wv = wp[lane + q * 32];
            #pragma unroll
            for (int bb = 0; bb < 8; ++bb) {
                float4 vv = ((const float4*)sv[bb])[lane + q * 32];
                acc[bb] += wv.x * vv.x + wv.y * vv.y + wv.z * vv.z + wv.w * vv.w;
            }
        }
        #pragma unroll
        for (int bb = 0; bb < 8; ++bb) {
            #pragma unroll
            for (int off = 16; off; off >>= 1)
                acc[bb] += __shfl_xor_sync(0xffffffffu, acc[bb], off);
        }
        if (lane == 0) {
            #pragma unroll
            for (int bb = 0; bb < 8; ++bb) so[bb][d] = acc[bb];
        }
    }
    __syncthreads();

    if (w < 8) {
        int b = b0 + w;
        float o1 = so[w][lane], o2 = so[w][lane + 32];
        if (bcast) { o1 *= (1.f / 32.f); o2 *= (1.f / 32.f); }
        float sq = o1 * o1 + o2 * o2;
        #pragma unroll
        for (int off = 16; off; off >>= 1) sq += __shfl_xor_sync(0xffffffffu, sq, off);
        float rn = rsqrtf(sq + EPSQ);
        o1 *= rn; o2 *= rn;
        out[((size_t)b * NCAP + n) * DCAP + lane]      = o1;
        out[((size_t)b * NCAP + n) * DCAP + lane + 32] = o2;
        so[w][lane]      = o1;
        so[w][lane + 32] = o2;
    }
    __syncthreads();

    if (dow) {
        int i = t;
        float acc[8] = {};
        #pragma unroll 8
        for (int d = 0; d < DCAP; ++d) {
            float wt = Wn[(size_t)d * DIN + i];
            #pragma unroll
            for (int bb = 0; bb < 8; ++bb) acc[bb] += so[bb][d] * wt;
        }
        #pragma unroll
        for (int bb = 0; bb < 8; ++bb)
            g_w[((size_t)(b0 + bb) * DIN + i) * NCAP + n] = acc[bb];
    }
}

// ---------------- fp16 MMA: logits[s,n] = U[s,:]·w[:,n], softmax fused ----------------
// grid (4 s-tiles, 64 b), block 256 (8 warps). Tile 128s x 32n; warp = 16s x 32n.
// Double-buffered smem, one sync per 32-k chunk.
__global__ __launch_bounds__(256) void blogmma_k() {
    int s0 = blockIdx.x * 128;
    int b  = blockIdx.y;
    __shared__ __align__(16) __half su[2][128 * 40];  // [s][k]
    __shared__ __align__(16) __half sw[2][32 * 40];   // [k][n]
    int t = threadIdx.x, w = t >> 5, lane = t & 31;
    int g = lane >> 2, tg = lane & 3;
    int wrow = w * 16;
    const __half* Ub = g_Uh + ((size_t)b * S_ + s0) * DIN;
    const float*  wb = g_w  + (size_t)b * DIN * NCAP;
    int arow = (lane & 7) + ((lane >> 3) & 1) * 8, acol = (lane >> 4) * 8;  // A non-trans
    int brow = arow, bcol = acol;                                           // B trans
    // loader coords: su rows sur, sur+64 (col quarter suq); sw row kk (t<128)
    int sur = t >> 2, suq = t & 3;
    int kk = t >> 2, q4 = t & 3;
    bool wload = (t < 128);
    float c[4][4] = {};
    uint4 pu[2], pwh;

    // prologue: chunk 0 -> buf0, prefetch chunk 1
    {
        pu[0] = *(const uint4*)(Ub + (size_t)sur * DIN + suq * 8);
        pu[1] = *(const uint4*)(Ub + (size_t)(sur + 64) * DIN + suq * 8);
        if (wload) {
            float4 w0 = *(const float4*)(wb + (size_t)kk * NCAP + q4 * 8);
            float4 w1 = *(const float4*)(wb + (size_t)kk * NCAP + q4 * 8 + 4);
            pwh.x = h2u(__floats2half2_rn(w0.x, w0.y));
            pwh.y = h2u(__floats2half2_rn(w0.z, w0.w));
            pwh.z = h2u(__floats2half2_rn(w1.x, w1.y));
            pwh.w = h2u(__floats2half2_rn(w1.z, w1.w));
        }
        *(uint4*)&su[0][sur * 40 + suq * 8]        = pu[0];
        *(uint4*)&su[0][(sur + 64) * 40 + suq * 8] = pu[1];
        if (wload) *(uint4*)&sw[0][kk * 40 + q4 * 8] = pwh;
        // prefetch chunk 1
        pu[0] = *(const uint4*)(Ub + (size_t)sur * DIN + 32 + suq * 8);
        pu[1] = *(const uint4*)(Ub + (size_t)(sur + 64) * DIN + 32 + suq * 8);
        if (wload) {
            float4 w0 = *(const float4*)(wb + (size_t)(32 + kk) * NCAP + q4 * 8);
            float4 w1 = *(const float4*)(wb + (size_t)(32 + kk) * NCAP + q4 * 8 + 4);
            pwh.x = h2u(__floats2half2_rn(w0.x, w0.y));
            pwh.y = h2u(__floats2half2_rn(w0.z, w0.w));
            pwh.z = h2u(__floats2half2_rn(w1.x, w1.y));
            pwh.w = h2u(__floats2half2_rn(w1.z, w1.w));
        }
    }
    __syncthreads();

    #pragma unroll 1
    for (int ch = 0; ch < 16; ++ch) {
        int cur = ch & 1, nxt = cur ^ 1;
        if (ch < 15) {   // stage chunk ch+1 (regs loaded last iteration)
            *(uint4*)&su[nxt][sur * 40 + suq * 8]        = pu[0];
            *(uint4*)&su[nxt][(sur + 64) * 40 + suq * 8] = pu[1];
            if (wload) *(uint4*)&sw[nxt][kk * 40 + q4 * 8] = pwh;
        }
        if (ch < 14) {   // prefetch chunk ch+2
            int k0 = (ch + 2) * 32;
            pu[0] = *(const uint4*)(Ub + (size_t)sur * DIN + k0 + suq * 8);
            pu[1] = *(const uint4*)(Ub + (size_t)(sur + 64) * DIN + k0 + suq * 8);
            if (wload) {
                float4 w0 = *(const float4*)(wb + (size_t)(k0 + kk) * NCAP + q4 * 8);
                float4 w1 = *(const float4*)(wb + (size_t)(k0 + kk) * NCAP + q4 * 8 + 4);
                pwh.x = h2u(__floats2half2_rn(w0.x, w0.y));
                pwh.y = h2u(__floats2half2_rn(w0.z, w0.w));
                pwh.z = h2u(__floats2half2_rn(w1.x, w1.y));
                pwh.w = h2u(__floats2half2_rn(w1.z, w1.w));
            }
        }
        #pragma unroll
        for (int ks = 0; ks < 32; ks += 16) {
            uint32_t a[4], bb2[2][4];
            ldsm4(a[0], a[1], a[2], a[3],
                  s2u(&su[cur][(wrow + arow) * 40 + ks + acol]));
            #pragma unroll
            for (int np = 0; np < 2; ++np)
                ldsm4t(bb2[np][0], bb2[np][1], bb2[np][2], bb2[np][3],
                       s2u(&sw[cur][(ks + brow) * 40 + np * 16 + bcol]));
            #pragma unroll
            for (int np = 0; np < 2; ++np) {
                mma_f16(c[2 * np][0], c[2 * np][1], c[2 * np][2], c[2 * np][3],
                        a[0], a[1], a[2], a[3], bb2[np][0], bb2[np][1]);
                mma_f16(c[2 * np + 1][0], c[2 * np + 1][1], c[2 * np + 1][2], c[2 * np + 1][3],
                        a[0], a[1], a[2], a[3], bb2[np][2], bb2[np][3]);
            }
        }
        __syncthreads();
    }
    // softmax over n per s-row (row's 32 n on 4 lanes sharing g: xor 1,2); fp16 store
    __half* cbase = g_ch + ((size_t)b * S_ + s0) * NCAP;
    #pragma unroll
    for (int half = 0; half < 2; ++half) {
        int row = wrow + g + half * 8;
        float v0 = c[0][half * 2], v1 = c[0][half * 2 + 1];
        float v2 = c[1][half * 2], v3 = c[1][half * 2 + 1];
        float v4 = c[2][half * 2], v5 = c[2][half * 2 + 1];
        float v6 = c[3][half * 2], v7 = c[3][half * 2 + 1];
        float m = fmaxf(fmaxf(fmaxf(v0, v1), fmaxf(v2, v3)),
                        fmaxf(fmaxf(v4, v5), fmaxf(v6, v7)));
        m = fmaxf(m, __shfl_xor_sync(0xffffffffu, m, 1));
        m = fmaxf(m, __shfl_xor_sync(0xffffffffu, m, 2));
        float e0 = __expf(v0 - m), e1 = __expf(v1 - m), e2 = __expf(v2 - m), e3 = __expf(v3 - m);
        float e4 = __expf(v4 - m), e5 = __expf(v5 - m), e6 = __expf(v6 - m), e7 = __expf(v7 - m);
        float sm = e0 + e1 + e2 + e3 + e4 + e5 + e6 + e7;
        sm += __shfl_xor_sync(0xffffffffu, sm, 1);
        sm += __shfl_xor_sync(0xffffffffu, sm, 2);
        float inv = 1.f / sm;
        __half2* cr = (__half2*)(cbase + (size_t)row * NCAP + 2 * tg);
        cr[0]  = __floats2half2_rn(e0 * inv, e1 * inv);
        cr[4]  = __floats2half2_rn(e2 * inv, e3 * inv);
        cr[8]  = __floats2half2_rn(e4 * inv, e5 * inv);
        cr[12] = __floats2half2_rn(e6 * inv, e7 * inv);
    }
}

// ---------------- fp16 MMA: v[n,i] = sum_s c[s,n] U[s,i] (v^T then transpose) ----------
// grid (4 i-tiles, 64 b), block 256 (8 warps). Tile 128i x 32n; warp = 16i x 32n.
// Double-buffered smem, one sync per 32-s chunk.
__global__ __launch_bounds__(256) void vmma_k() {
    int i0 = blockIdx.x * 128;
    int b  = blockIdx.y;
    __shared__ __align__(16) unsigned char smraw[22528];
    __half (*su)[32 * 136] = (__half(*)[32 * 136])smraw;           // 2 x 8704B
    __half (*sc)[32 * 40]  = (__half(*)[32 * 40])(smraw + 17408);  // 2 x 2560B
    float* vsm = (float*)smraw;                                    // epilogue: 128x33 floats
    int t = threadIdx.x, w = t >> 5, lane = t & 31;
    int g = lane >> 2, tg = lane & 3;
    int wi = w * 16;
    // ldmatrix.trans lane offsets
    int tarow = (lane & 7) + ((lane >> 4) & 1) * 8, tacol = ((lane >> 3) & 1) * 8;  // A
    int tbrow = (lane & 7) + ((lane >> 3) & 1) * 8, tbcol = (lane >> 4) * 8;        // B
    const __half* Ub = g_Uh + (size_t)b * S_ * DIN;
    const __half* cb = g_ch + (size_t)b * S_ * NCAP;
    // loader coords: su rows vr, vr+16 (col 16th vq); sc row cr_ (t<128)
    int vr = t >> 4, vq = t & 15;
    int cr_ = t >> 2, cq = t & 3;
    bool cload = (t < 128);
    float c[4][4] = {};
    uint4 pu[2], pc;

    // prologue
    {
        pu[0] = *(const uint4*)(Ub + (size_t)vr * DIN + i0 + vq * 8);
        pu[1] = *(const uint4*)(Ub + (size_t)(vr + 16) * DIN + i0 + vq * 8);
        if (cload) pc = *(const uint4*)(cb + (size_t)cr_ * NCAP + cq * 8);
        *(uint4*)&su[0][vr * 136 + vq * 8]        = pu[0];
        *(uint4*)&su[0][(vr + 16) * 136 + vq * 8] = pu[1];
        if (cload) *(uint4*)&sc[0][cr_ * 40 + cq * 8] = pc;
        pu[0] = *(const uint4*)(Ub + (size_t)(32 + vr) * DIN + i0 + vq * 8);
        pu[1] = *(const uint4*)(Ub + (size_t)(32 + vr + 16) * DIN + i0 + vq * 8);
        if (cload) pc = *(const uint4*)(cb + (size_t)(32 + cr_) * NCAP + cq * 8);
    }
    __syncthreads();

    #pragma unroll 1
    for (int ch = 0; ch < 16; ++ch) {
        int cur = ch & 1, nxt = cur ^ 1;
        if (ch < 15) {
            *(uint4*)&su[nxt][vr * 136 + vq * 8]        = pu[0];
            *(uint4*)&su[nxt][(vr + 16) * 136 + vq * 8] = pu[1];
            if (cload) *(uint4*)&sc[nxt][cr_ * 40 + cq * 8] = pc;
        }
        if (ch < 14) {
            int s1 = (ch + 2) * 32;
            pu[0] = *(const uint4*)(Ub + (size_t)(s1 + vr) * DIN + i0 + vq * 8);
            pu[1] = *(const uint4*)(Ub + (size_t)(s1 + vr + 16) * DIN + i0 + vq * 8);
            if (cload) pc = *(const uint4*)(cb + (size_t)(s1 + cr_) * NCAP + cq * 8);
        }
        #pragma unroll
        for (int ks = 0; ks < 32; ks += 16) {
            uint32_t a[4], bb2[2][4];
            ldsm4t(a[0], a[1], a[2], a[3],
                   s2u(&su[cur][(ks + tarow) * 136 + wi + tacol]));
            #pragma unroll
            for (int np = 0; np < 2; ++np)
                ldsm4t(bb2[np][0], bb2[np][1], bb2[np][2], bb2[np][3],
                       s2u(&sc[cur][(ks + tbrow) * 40 + np * 16 + tbcol]));
            #pragma unroll
            for (int np = 0; np < 2; ++np) {
                mma_f16(c[2 * np][0], c[2 * np][1], c[2 * np][2], c[2 * np][3],
                        a[0], a[1], a[2], a[3], bb2[np][0], bb2[np][1]);
                mma_f16(c[2 * np + 1][0], c[2 * np + 1][1], c[2 * np + 1][2], c[2 * np + 1][3],
                        a[0], a[1], a[2], a[3], bb2[np][2], bb2[np][3]);
            }
        }
        __syncthreads();
    }
    // transpose v^T[i][n] -> v[n][i] via smem, coalesced store
    #pragma unroll
    for (int nt = 0; nt < 4; ++nt) {
        int nc = nt * 8 + 2 * tg;
        vsm[(wi + g)     * 33 + nc]     = c[nt][0];
        vsm[(wi + g)     * 33 + nc + 1] = c[nt][1];
        vsm[(wi + g + 8) * 33 + nc]     = c[nt][2];
        vsm[(wi + g + 8) * 33 + nc + 1] = c[nt][3];
    }
    __syncthreads();
    {
        int n = t >> 3, igrp = t & 7;
        float* vb = g_v + ((size_t)b * NCAP + n) * DIN + i0;
        #pragma unroll
        for (int q = 0; q < 4; ++q) {
            int i4 = igrp * 4 + q * 32;
            float4 o = make_float4(vsm[(i4 + 0) * 33 + n], vsm[(i4 + 1) * 33 + n],
                                   vsm[(i4 + 2) * 33 + n], vsm[(i4 + 3) * 33 + n]);
            *(float4*)(vb + i4) = o;
        }
    }
}

// ---------------- launch ----------------
extern "C" void kernel_launch(void* const* d_in, const int* in_sizes, int n_in,
                              void* d_out, int out_size) {
    const float* U = (const float*)d_in[0];   // (64, 512, 512)
    const float* W = (const float*)d_in[1];   // (512, 2048)
    float* out = (float*)d_out;               // (64, 32, 64)

    prep_k<<<512, 256>>>(U, W);
    outw_k<<<dim3(32, 8), 512>>>(out, 1, 1);             // iteration 0 + w0
    for (int it = 0; it < 2; ++it) {
        blogmma_k<<<dim3(4, 64), 256>>>();
        vmma_k<<<dim3(4, 64), 256>>>();
        outw_k<<<dim3(32, 8), 512>>>(out, 0, it == 0);   // out + (w for iter 1 only)
    }
}